// round 4
// baseline (speedup 1.0000x reference)
#include <cuda_runtime.h>

#define FULL_MASK 0xFFFFFFFFu

constexpr int H = 512;
constexpr int W = 512;
constexpr int NPLANE = 8 * 16;           // 128 independent (B,C) planes
constexpr int STRIP_OUT = 28;            // useful output columns per warp
constexpr int NSTRIP = (W + STRIP_OUT - 1) / STRIP_OUT;   // 19
constexpr int SEG = 128;                 // rows per warp task (2 pipelines x 64)
constexpr int HSEG = 64;                 // rows per pipeline
constexpr int NSEG = H / SEG;            // 4
constexpr int WARPS_PER_BLOCK = 4;
constexpr int NTASK = NPLANE * NSTRIP * NSEG;             // 9728
constexpr int NBLOCK = NTASK / WARPS_PER_BLOCK;           // 2432

// All-scalar pipeline state: 21 floats, ring period 3, slot 2 = newest.
struct Pipe {
    float hI0, hI1, hI2;
    float hP0, hP1, hP2;
    float hII0, hII1, hII2;
    float hIP0, hIP1, hIP2;
    float hA0, hA1, hA2;
    float hB0, hB1, hB2;
    float I0, I1, I2;
};

__global__ void __launch_bounds__(WARPS_PER_BLOCK * 32)
guided_filter_kernel(const float* __restrict__ gI,
                     const float* __restrict__ gP,
                     float* __restrict__ gO)
{
    const int lane = threadIdx.x & 31;
    const int task = blockIdx.x * WARPS_PER_BLOCK + (threadIdx.x >> 5);

    const int pl  = task / (NSTRIP * NSEG);
    const int rem = task - pl * (NSTRIP * NSEG);
    const int sx  = rem >> 2;            // / NSEG (NSEG==4)
    const int sy  = rem & 3;

    const int x = sx * STRIP_OUT - 2 + lane;     // lanes 0,1,30,31 = halo
    const bool xin = ((unsigned)x < (unsigned)W);
    const bool outok = (lane >= 2) && (lane <= 29) && (x < W);

    const size_t pbase = (size_t)pl * (size_t)(H * W);
    const float* baseI = gI + pbase;
    const float* baseP = gP + pbase;
    float*       baseO = gO + pbase;

    // Horizontal window count (count_include_pad=False): 3 interior, 2 edges
    const float cxf  = (x >= 1 && x <= W - 2) ? 3.0f : 2.0f;
    const float inv3 = 1.0f / (3.0f * cxf);
    const float inv2 = 1.0f / (2.0f * cxf);

    const int rA = sy * SEG;            // pipeline A: output rows rA..rA+63
    const int rB = rA + HSEG;           // pipeline B: output rows rB..rB+63

    Pipe A = {}, B = {};

    // -------- per-pipe helpers (independent chains) --------
    auto hsum = [&](Pipe& q, float Iv, float Pv) {
        q.hI0 = q.hI1;  q.hI1 = q.hI2;
        q.hP0 = q.hP1;  q.hP1 = q.hP2;
        q.hII0 = q.hII1; q.hII1 = q.hII2;
        q.hIP0 = q.hIP1; q.hIP1 = q.hIP2;
        q.I0 = q.I1; q.I1 = q.I2;
        const float Il = __shfl_up_sync(FULL_MASK, Iv, 1);
        const float Ir = __shfl_down_sync(FULL_MASK, Iv, 1);
        const float Pl = __shfl_up_sync(FULL_MASK, Pv, 1);
        const float Pr = __shfl_down_sync(FULL_MASK, Pv, 1);
        q.hI2  = Il + Iv + Ir;
        q.hP2  = Pl + Pv + Pr;
        q.hII2 = Il * Il + Iv * Iv + Ir * Ir;
        q.hIP2 = Il * Pl + Iv * Pv + Ir * Pr;
        q.I2 = Iv;
    };

    auto step_ab = [&](Pipe& q, int ry) {
        const float invc = (ry >= 1 && ry <= H - 2) ? inv3 : inv2;
        const float mI  = (q.hI0  + q.hI1  + q.hI2 ) * invc;
        const float mP  = (q.hP0  + q.hP1  + q.hP2 ) * invc;
        const float mII = (q.hII0 + q.hII1 + q.hII2) * invc;
        const float mIP = (q.hIP0 + q.hIP1 + q.hIP2) * invc;
        float a = __fdividef(mIP - mI * mP, (mII - mI * mI) + 0.01f);
        float b = mP - a * mI;
        if (!(xin && (unsigned)ry < (unsigned)H)) { a = 0.f; b = 0.f; }
        const float al = __shfl_up_sync(FULL_MASK, a, 1);
        const float ar = __shfl_down_sync(FULL_MASK, a, 1);
        const float bl = __shfl_up_sync(FULL_MASK, b, 1);
        const float br = __shfl_down_sync(FULL_MASK, b, 1);
        q.hA0 = q.hA1; q.hA1 = q.hA2;
        q.hB0 = q.hB1; q.hB1 = q.hB2;
        q.hA2 = al + a + ar;
        q.hB2 = bl + b + br;
    };

    auto step_out = [&](Pipe& q, int ro, int off) {
        const float invo = (ro >= 1 && ro <= H - 2) ? inv3 : inv2;
        const float SA = q.hA0 + q.hA1 + q.hA2;
        const float SB = q.hB0 + q.hB1 + q.hB2;
        const float o = (SA * q.I0 + SB) * invo;   // shared normalization
        if (outok) baseO[off] = o;
    };

    // -------- interleaved dual pipeline --------
    int yA = rA - 2,        yB = rB - 2;
    int offA = yA * W + x,  offB = yB * W + x;

    // Prologue: prime rings on 4 rows each.
#pragma unroll
    for (int it = 0; it < 4; ++it) {
        float IvA = 0.f, PvA = 0.f, IvB = 0.f, PvB = 0.f;
        if (xin && (unsigned)yA < (unsigned)H) { IvA = __ldg(baseI + offA); PvA = __ldg(baseP + offA); }
        if (xin && (unsigned)yB < (unsigned)H) { IvB = __ldg(baseI + offB); PvB = __ldg(baseP + offB); }
        hsum(A, IvA, PvA);
        hsum(B, IvB, PvB);
        if (it >= 2) { step_ab(A, yA - 1); step_ab(B, yB - 1); }
        yA++; yB++; offA += W; offB += W;
    }

    // Steady state: 64 iterations, each produces one row per pipeline.
    int ooA = rA * W + x;
    int ooB = rB * W + x;
#pragma unroll 3
    for (int it = 0; it < HSEG; ++it) {
        float IvA = 0.f, PvA = 0.f, IvB = 0.f, PvB = 0.f;
        if (xin && (unsigned)yA < (unsigned)H) { IvA = __ldg(baseI + offA); PvA = __ldg(baseP + offA); }
        if (xin && (unsigned)yB < (unsigned)H) { IvB = __ldg(baseI + offB); PvB = __ldg(baseP + offB); }
        hsum(A, IvA, PvA);
        hsum(B, IvB, PvB);
        step_ab(A, yA - 1);
        step_ab(B, yB - 1);
        step_out(A, yA - 2, ooA);
        step_out(B, yB - 2, ooB);
        yA++; yB++; offA += W; offB += W; ooA += W; ooB += W;
    }
}

extern "C" void kernel_launch(void* const* d_in, const int* in_sizes, int n_in,
                              void* d_out, int out_size) {
    const float* I = (const float*)d_in[0];   // input
    const float* P = (const float*)d_in[1];   // guide
    float* O = (float*)d_out;
    guided_filter_kernel<<<NBLOCK, WARPS_PER_BLOCK * 32>>>(I, P, O);
}

// round 6
// speedup vs baseline: 1.2505x; 1.2505x over previous
#include <cuda_runtime.h>

#define FULL_MASK 0xFFFFFFFFu

constexpr int H = 512;
constexpr int W = 512;
constexpr int NPLANE = 8 * 16;         // 128 independent planes
constexpr int CPL = 4;                 // columns per lane (float4)
constexpr int USEFUL = 120;            // stored cols per warp (lanes 1..30)
constexpr int NSTRIP = 5;              // ceil(512 / 120)
constexpr int SEG = 64;                // output rows per warp task
constexpr int NSEG = H / SEG;          // 8
constexpr int WPB = 4;                 // warps per block
constexpr int NTASK = NPLANE * NSTRIP * NSEG;   // 5120
constexpr int NBLOCK = NTASK / WPB;             // 1280

__global__ void __launch_bounds__(WPB * 32, 4)
guided_filter_kernel(const float* __restrict__ gI,
                     const float* __restrict__ gP,
                     float* __restrict__ gO)
{
    const int lane = threadIdx.x & 31;
    const int task = blockIdx.x * WPB + (threadIdx.x >> 5);

    const int pl  = task / (NSTRIP * NSEG);
    const int rem = task - pl * (NSTRIP * NSEG);
    const int sx  = rem >> 3;          // / NSEG
    const int sy  = rem & 7;

    // Lane owns columns x0 .. x0+3. xb = 120*sx - 4 is 4-aligned, so every
    // lane's float4 is either fully inside [0,W) or fully outside.
    const int xb = sx * USEFUL - 4;
    const int x0 = xb + CPL * lane;
    const bool vecok = (x0 >= 0) && (x0 + 3 < W);
    const bool stok  = vecok && (lane >= 1) && (lane <= 30);

    const size_t pbase = (size_t)pl * (size_t)(H * W);
    const float* baseI = gI + pbase;
    const float* baseP = gP + pbase;
    float*       baseO = gO + pbase;

    // Per-column horizontal normalization (cy=3 case): 1/(3*cx), cx in {2,3}.
    // CRITICAL: 0 for columns outside [0,W) -> forces a=b=0 exactly there
    // (cov=var=0 -> a=0/(eps)=0, b=0), so boundary shuffles can't leak
    // nonzero a,b into the second blur (count_include_pad=False semantics).
    float inv3[CPL];
#pragma unroll
    for (int j = 0; j < CPL; ++j) {
        const int xc = x0 + j;
        const float cx = (xc >= 1 && xc <= W - 2) ? 3.0f : 2.0f;
        inv3[j] = ((unsigned)xc < (unsigned)W) ? 1.0f / (3.0f * cx) : 0.0f;
    }

    const int r0 = sy * SEG;

    // Ring buffers, period 3, slot 2 = newest row. All constant-indexed.
    float hI[3][CPL], hP[3][CPL], hII[3][CPL], hIP[3][CPL], hA[3][CPL], hB[3][CPL];
#pragma unroll
    for (int k = 0; k < 3; ++k)
#pragma unroll
        for (int j = 0; j < CPL; ++j) {
            hI[k][j] = 0.f; hP[k][j] = 0.f; hII[k][j] = 0.f;
            hIP[k][j] = 0.f; hA[k][j] = 0.f; hB[k][j] = 0.f;
        }

    // ---- stage 1: load row y, horizontal 1x3 sums into slot 2 ----
    auto stage_load = [&](int y) {
#pragma unroll
        for (int j = 0; j < CPL; ++j) {
            hI[0][j] = hI[1][j];   hI[1][j] = hI[2][j];
            hP[0][j] = hP[1][j];   hP[1][j] = hP[2][j];
            hII[0][j] = hII[1][j]; hII[1][j] = hII[2][j];
            hIP[0][j] = hIP[1][j]; hIP[1][j] = hIP[2][j];
        }
        float4 Iv = make_float4(0.f, 0.f, 0.f, 0.f);
        float4 Pv = make_float4(0.f, 0.f, 0.f, 0.f);
        if (vecok && (unsigned)y < (unsigned)H) {
            const size_t off = (size_t)y * W + x0;
            Iv = *reinterpret_cast<const float4*>(baseI + off);
            Pv = *reinterpret_cast<const float4*>(baseP + off);
        }
        const float Il = __shfl_up_sync(FULL_MASK, Iv.w, 1);
        const float Ir = __shfl_down_sync(FULL_MASK, Iv.x, 1);
        const float Pl = __shfl_up_sync(FULL_MASK, Pv.w, 1);
        const float Pr = __shfl_down_sync(FULL_MASK, Pv.x, 1);

        // hI
        const float i01 = Iv.x + Iv.y, i12 = Iv.y + Iv.z, i23 = Iv.z + Iv.w;
        hI[2][0] = Il + i01;  hI[2][1] = i01 + Iv.z;
        hI[2][2] = i12 + Iv.w; hI[2][3] = i23 + Ir;
        // hP
        const float p01 = Pv.x + Pv.y, p12 = Pv.y + Pv.z, p23 = Pv.z + Pv.w;
        hP[2][0] = Pl + p01;  hP[2][1] = p01 + Pv.z;
        hP[2][2] = p12 + Pv.w; hP[2][3] = p23 + Pr;
        // hII
        const float t0 = Iv.x * Iv.x, t1 = Iv.y * Iv.y, t2 = Iv.z * Iv.z, t3 = Iv.w * Iv.w;
        const float u01 = t0 + t1, u12 = t1 + t2, u23 = t2 + t3;
        hII[2][0] = fmaf(Il, Il, u01); hII[2][1] = u01 + t2;
        hII[2][2] = u12 + t3;          hII[2][3] = fmaf(Ir, Ir, u23);
        // hIP
        const float q0 = Iv.x * Pv.x, q1 = Iv.y * Pv.y, q2 = Iv.z * Pv.z, q3 = Iv.w * Pv.w;
        const float v01 = q0 + q1, v12 = q1 + q2, v23 = q2 + q3;
        hIP[2][0] = fmaf(Il, Pl, v01); hIP[2][1] = v01 + q2;
        hIP[2][2] = v12 + q3;          hIP[2][3] = fmaf(Ir, Pr, v23);
    };

    // ---- stage 2: 3x3 means at row ry -> a,b; horizontal sums of a,b ----
    // fy: 0 for out-of-image rows (forces a=b=0 exactly), 1.5 at y-edges
    // (cy=2), 1 interior.
    auto stage_ab = [&](int ry) {
        const float fy = ((unsigned)ry < (unsigned)H)
                           ? ((ry == 0 || ry == H - 1) ? 1.5f : 1.0f) : 0.0f;
        float a[CPL], b[CPL];
#pragma unroll
        for (int j = 0; j < CPL; ++j) {
            const float invc = fy * inv3[j];
            const float SI  = hI[0][j]  + hI[1][j]  + hI[2][j];
            const float SP  = hP[0][j]  + hP[1][j]  + hP[2][j];
            const float SII = hII[0][j] + hII[1][j] + hII[2][j];
            const float SIP = hIP[0][j] + hIP[1][j] + hIP[2][j];
            const float mI  = SI  * invc;
            const float mP  = SP  * invc;
            const float mII = SII * invc;
            const float mIP = SIP * invc;
            const float var = fmaf(-mI, mI, mII);
            const float cov = fmaf(-mI, mP, mIP);
            const float av  = __fdividef(cov, var + 0.01f);
            a[j] = av;
            b[j] = fmaf(-av, mI, mP);
        }
        const float al = __shfl_up_sync(FULL_MASK, a[3], 1);
        const float ar = __shfl_down_sync(FULL_MASK, a[0], 1);
        const float bl = __shfl_up_sync(FULL_MASK, b[3], 1);
        const float br = __shfl_down_sync(FULL_MASK, b[0], 1);
#pragma unroll
        for (int j = 0; j < CPL; ++j) {
            hA[0][j] = hA[1][j]; hA[1][j] = hA[2][j];
            hB[0][j] = hB[1][j]; hB[1][j] = hB[2][j];
        }
        const float a01 = a[0] + a[1], a12 = a[1] + a[2], a23 = a[2] + a[3];
        hA[2][0] = al + a01;  hA[2][1] = a01 + a[2];
        hA[2][2] = a12 + a[3]; hA[2][3] = a23 + ar;
        const float b01 = b[0] + b[1], b12 = b[1] + b[2], b23 = b[2] + b[3];
        hB[2][0] = bl + b01;  hB[2][1] = b01 + b[2];
        hB[2][2] = b12 + b[3]; hB[2][3] = b23 + br;
    };

    // ---- stage 3: blur a,b at row ro, combine with reloaded I, store ----
    auto stage_out = [&](int ro) {
        const float fo = (ro == 0 || ro == H - 1) ? 1.5f : 1.0f;
        float4 Iv = make_float4(0.f, 0.f, 0.f, 0.f);
        const size_t off = (size_t)ro * W + x0;
        if (vecok) Iv = *reinterpret_cast<const float4*>(baseI + off);
        float o[CPL];
        const float Ic[CPL] = {Iv.x, Iv.y, Iv.z, Iv.w};
#pragma unroll
        for (int j = 0; j < CPL; ++j) {
            const float invo = fo * inv3[j];
            const float SA = hA[0][j] + hA[1][j] + hA[2][j];
            const float SB = hB[0][j] + hB[1][j] + hB[2][j];
            o[j] = fmaf(SA, Ic[j], SB) * invo;
        }
        if (stok) {
            *reinterpret_cast<float4*>(baseO + off) =
                make_float4(o[0], o[1], o[2], o[3]);
        }
    };

    // Prologue: prime rings on rows r0-2 .. r0+1.
#pragma unroll
    for (int it = 0; it < 4; ++it) {
        const int y = r0 - 2 + it;
        stage_load(y);
        if (it >= 2) stage_ab(y - 1);
    }
    // Steady state: y = r0+2 .. r0+65; out rows r0 .. r0+63.
#pragma unroll 3
    for (int it = 0; it < SEG; ++it) {
        const int y = r0 + 2 + it;
        stage_load(y);
        stage_ab(y - 1);
        stage_out(y - 2);
    }
}

extern "C" void kernel_launch(void* const* d_in, const int* in_sizes, int n_in,
                              void* d_out, int out_size) {
    const float* I = (const float*)d_in[0];   // input
    const float* P = (const float*)d_in[1];   // guide
    float* O = (float*)d_out;
    guided_filter_kernel<<<NBLOCK, WPB * 32>>>(I, P, O);
}